// round 3
// baseline (speedup 1.0000x reference)
#include <cuda_runtime.h>
#include <math.h>

// Fixed problem shape (B, N, M) = (64, 2048, 256)
#define BB 64
#define NN 2048
#define MM 256
#define EPS_COS 1e-16f
#define EPS_NRM 1e-8f
#define NSPLIT 16   // split-N factor for the read reduction

// Static scratch (allocation-free rule)
__device__ float g_scores[BB * NN];   // dot/mem_nrm  (k_nrm applied later)
__device__ float g_a[BB * NN];        // w_r * (1 - w_lu_prev)
__device__ float g_part[BB * NSPLIT * MM];

// -------------------------------------------------------------------
// Kernel 1: per (b,n) row — fused dot(mem+eps, k+eps) and ||mem+eps||.
// Stores dot/mem_nrm; the per-b 1/k_nrm scale is applied in softmax.
// One warp per row, 8 floats per lane (2x float4). Block = 256 (8 rows).
// grid = B*N/8 = 16384
// -------------------------------------------------------------------
__global__ void score_kernel(const float4* __restrict__ mem4,
                             const float* __restrict__ k) {
    int warp = threadIdx.x >> 5;
    int lane = threadIdx.x & 31;
    int row  = blockIdx.x * 8 + warp;          // row in [0, B*N)
    int b    = row >> 11;                      // N = 2048; 8 rows never straddle b

    __shared__ float ke[MM];
    ke[threadIdx.x] = k[b * MM + threadIdx.x] + EPS_COS;
    __syncthreads();

    const float4* p = mem4 + (size_t)row * (MM / 4) + lane * 2;
    float4 v0 = p[0];
    float4 v1 = p[1];
    int m0 = lane * 8;

    float dot = 0.f, ss = 0.f, me;
    me = v0.x + EPS_COS; dot = fmaf(me, ke[m0 + 0], dot); ss = fmaf(me, me, ss);
    me = v0.y + EPS_COS; dot = fmaf(me, ke[m0 + 1], dot); ss = fmaf(me, me, ss);
    me = v0.z + EPS_COS; dot = fmaf(me, ke[m0 + 2], dot); ss = fmaf(me, me, ss);
    me = v0.w + EPS_COS; dot = fmaf(me, ke[m0 + 3], dot); ss = fmaf(me, me, ss);
    me = v1.x + EPS_COS; dot = fmaf(me, ke[m0 + 4], dot); ss = fmaf(me, me, ss);
    me = v1.y + EPS_COS; dot = fmaf(me, ke[m0 + 5], dot); ss = fmaf(me, me, ss);
    me = v1.z + EPS_COS; dot = fmaf(me, ke[m0 + 6], dot); ss = fmaf(me, me, ss);
    me = v1.w + EPS_COS; dot = fmaf(me, ke[m0 + 7], dot); ss = fmaf(me, me, ss);

    #pragma unroll
    for (int o = 16; o; o >>= 1) {
        dot += __shfl_xor_sync(0xffffffffu, dot, o);
        ss  += __shfl_xor_sync(0xffffffffu, ss,  o);
    }
    if (lane == 0) {
        float nrm = fmaxf(sqrtf(ss), EPS_NRM);
        g_scores[row] = dot / nrm;
    }
}

// -------------------------------------------------------------------
// Kernel 2: per-b: compute k_nrm, scale logits, softmax over N=2048,
//           a[b,n] = w_r*(1-lu), c = sum(w_r*w_w), out[b,m] = c*k[b,m]
// grid = B, block = 256 (8 scores per thread)
// -------------------------------------------------------------------
__global__ void softmax_kernel(const float* __restrict__ k,
                               const float* __restrict__ g,
                               const float* __restrict__ w_prev,
                               const int*   __restrict__ w_lu_prev,
                               float* __restrict__ out) {
    int b = blockIdx.x;
    int t = threadIdx.x;
    int lane = t & 31, wid = t >> 5;
    __shared__ float red[8];

    // ---- k_nrm for this b ----
    float kv = k[b * MM + t];
    float ke = kv + EPS_COS;
    float ss = ke * ke;
    #pragma unroll
    for (int o = 16; o; o >>= 1) ss += __shfl_xor_sync(0xffffffffu, ss, o);
    if (lane == 0) red[wid] = ss;
    __syncthreads();
    float kn = 0.f;
    #pragma unroll
    for (int i = 0; i < 8; i++) kn += red[i];
    float inv_knrm = 1.f / fmaxf(sqrtf(kn), EPS_NRM);
    __syncthreads();

    // ---- softmax over scaled logits ----
    float s[8];
    float mx = -1e30f;
    #pragma unroll
    for (int i = 0; i < 8; i++) {
        s[i] = g_scores[b * NN + i * 256 + t] * inv_knrm;
        mx = fmaxf(mx, s[i]);
    }
    #pragma unroll
    for (int o = 16; o; o >>= 1) mx = fmaxf(mx, __shfl_xor_sync(0xffffffffu, mx, o));
    if (lane == 0) red[wid] = mx;
    __syncthreads();
    float bm = red[0];
    #pragma unroll
    for (int i = 1; i < 8; i++) bm = fmaxf(bm, red[i]);
    __syncthreads();

    float e[8], sum = 0.f;
    #pragma unroll
    for (int i = 0; i < 8; i++) { e[i] = __expf(s[i] - bm); sum += e[i]; }
    #pragma unroll
    for (int o = 16; o; o >>= 1) sum += __shfl_xor_sync(0xffffffffu, sum, o);
    if (lane == 0) red[wid] = sum;
    __syncthreads();
    float tot = 0.f;
    #pragma unroll
    for (int i = 0; i < 8; i++) tot += red[i];
    __syncthreads();

    // ---- a, c, and the k-rank-1 part of the output ----
    float inv = 1.f / tot;
    float gb  = g[b];
    float c   = 0.f;
    #pragma unroll
    for (int i = 0; i < 8; i++) {
        int n = i * 256 + t;
        float wr  = e[i] * inv;
        float lu  = (float)w_lu_prev[b * NN + n];
        float wrp = w_prev[b * 2 * NN + NN + n];      // w_prev[b,1,n]
        float ww  = gb * wrp + (1.f - gb) * lu;
        g_a[b * NN + n] = wr * (1.f - lu);
        c += wr * ww;
    }
    #pragma unroll
    for (int o = 16; o; o >>= 1) c += __shfl_xor_sync(0xffffffffu, c, o);
    if (lane == 0) red[wid] = c;
    __syncthreads();
    float ctot = 0.f;
    #pragma unroll
    for (int i = 0; i < 8; i++) ctot += red[i];

    out[b * MM + t] = ctot * kv;
}

// -------------------------------------------------------------------
// Kernel 3: partial read reduction. grid = (NSPLIT, B), block = 256.
// Threads = 4 n-slices x 64 float4-columns. Each thread streams its
// n-slice with LDG.128 (unroll 4 -> MLP~4), accumulates float4, then a
// small smem reduce combines the 4 slices.
// part[b,split,m] = sum over 128 n of a[b,n]*mem[b,n,m]   (deterministic)
// -------------------------------------------------------------------
__global__ void read_part_kernel(const float4* __restrict__ mem4) {
    int b     = blockIdx.y;
    int split = blockIdx.x;
    int t     = threadIdx.x;
    int c4    = t & 63;          // float4 column in [0,64)
    int slice = t >> 6;          // n-slice in [0,4)
    const int CHUNK = NN / NSPLIT;   // 128 rows per block

    __shared__ float a[CHUNK];
    __shared__ float4 red[256];
    int n0 = split * CHUNK;
    if (t < CHUNK) a[t] = g_a[b * NN + n0 + t];
    __syncthreads();

    // row pointer: mem4[(b*NN + n0 + i) * 64 + c4]
    const float4* p = mem4 + ((size_t)(b * NN + n0)) * 64 + c4;
    float4 acc = make_float4(0.f, 0.f, 0.f, 0.f);
    #pragma unroll 4
    for (int i = slice; i < CHUNK; i += 4) {
        float4 v = p[(size_t)i * 64];
        float  w = a[i];
        acc.x = fmaf(w, v.x, acc.x);
        acc.y = fmaf(w, v.y, acc.y);
        acc.z = fmaf(w, v.z, acc.z);
        acc.w = fmaf(w, v.w, acc.w);
    }
    red[t] = acc;
    __syncthreads();

    if (slice == 0) {
        float4 r0 = red[c4], r1 = red[c4 + 64], r2 = red[c4 + 128], r3 = red[c4 + 192];
        float4 s;
        s.x = (r0.x + r1.x) + (r2.x + r3.x);
        s.y = (r0.y + r1.y) + (r2.y + r3.y);
        s.z = (r0.z + r1.z) + (r2.z + r3.z);
        s.w = (r0.w + r1.w) + (r2.w + r3.w);
        ((float4*)g_part)[(b * NSPLIT + split) * 64 + c4] = s;
    }
}

// -------------------------------------------------------------------
// Kernel 4: out[b,m] += sum over splits of part[b,split,m]
// grid = B, block = 256
// -------------------------------------------------------------------
__global__ void read_final_kernel(float* __restrict__ out) {
    int b = blockIdx.x;
    int t = threadIdx.x;
    float acc = 0.f;
    #pragma unroll
    for (int s = 0; s < NSPLIT; s++) acc += g_part[(b * NSPLIT + s) * MM + t];
    out[b * MM + t] += acc;
}

// -------------------------------------------------------------------
extern "C" void kernel_launch(void* const* d_in, const int* in_sizes, int n_in,
                              void* d_out, int out_size) {
    const float* memory    = (const float*)d_in[0];   // (B,N,M)
    const float* k         = (const float*)d_in[1];   // (B,M)
    const float* g         = (const float*)d_in[2];   // (B,1)
    // d_in[3] = gamma  -> dead code w.r.t. output
    const float* w_prev    = (const float*)d_in[4];   // (B,2,N)
    const int*   w_lu_prev = (const int*)  d_in[5];   // (B,N)
    // d_in[6] = n      -> dead code w.r.t. output
    float* out = (float*)d_out;                        // (B,M)

    score_kernel<<<BB * NN / 8, 256>>>((const float4*)memory, k);
    softmax_kernel<<<BB, 256>>>(k, g, w_prev, w_lu_prev, out);
    read_part_kernel<<<dim3(NSPLIT, BB), 256>>>((const float4*)memory);
    read_final_kernel<<<BB, 256>>>(out);
}